// round 9
// baseline (speedup 1.0000x reference)
#include <cuda_runtime.h>
#include <cuda_bf16.h>
#include <math.h>

// ---------------- problem constants ----------------
#define Bz   16
#define Nn   1024
#define Hh   64
#define NB   64
#define NT   16          // Nn / NB
#define ETA_ 0.01f

// output layout (tuple order, flattened)
#define SP_OFF    0
#define DEC_OFF   32
#define GAMMA_OFF (32 + Bz*Nn*Hh)            // 1048608
#define PROP_OFF  (GAMMA_OFF + Bz*Nn)        // 1064992

// ---------------- device scratch (static, no runtime alloc) ----------------
__device__ __align__(16) float2 g_A[Bz][Nn][Nn];                 // working -> inverses (134 MB)
__device__ __align__(16) __nv_bfloat16 g_FS[Bz][8][6][128][64];  // F splits  (12.6 MB, swizzled)
__device__ __align__(16) __nv_bfloat16 g_BS[Bz][NT][9][64][64];  // Rk splits (18.9 MB, swizzled)
__device__ float g_Hs[Nn][Nn];
__device__ float g_cell[Bz][Hh];
__device__ float g_omega[Bz][Nn];
__device__ float g_wre[Bz];

// pass tables: 24 unit GEMM passes (A-split, B-split, accumulator)
// A splits: 0=Frh 1=Frm 2=Frl 3=Fih 4=Fim 5=Fil
// B splits: 0=Rrh 1=Rrm 2=Rrl 3=Rih 4=Rim 5=Ril 6=-Rih 7=-Rim 8=-Ril
__constant__ int c_sa[24] = {0,0,0,1,1,2, 3,3,3,4,4,5,  0,0,0,1,1,2, 3,3,3,4,4,5};
__constant__ int c_sb[24] = {0,1,2,0,1,0, 6,7,8,6,7,6,  3,4,5,3,4,3, 0,1,2,0,1,0};
__constant__ int c_ac[24] = {0,0,0,0,0,0, 0,0,0,0,0,0,  1,1,1,1,1,1, 1,1,1,1,1,1};

// ---------------- packed f32x2 helpers (rowscale) ----------------
__device__ __forceinline__ unsigned long long pack2(float x, float y) {
    unsigned long long r;
    asm("mov.b64 %0, {%1, %2};" : "=l"(r) : "f"(x), "f"(y));
    return r;
}
__device__ __forceinline__ void unpack2(unsigned long long v, float& x, float& y) {
    asm("mov.b64 {%0, %1}, %2;" : "=f"(x), "=f"(y) : "l"(v));
}
__device__ __forceinline__ void ffma2(unsigned long long& d,
                                      unsigned long long a, unsigned long long b) {
    asm("fma.rn.f32x2 %0, %1, %2, %0;" : "+l"(d) : "l"(a), "l"(b));
}

__device__ __forceinline__ void cgemm2_body(const float2 (*Ls)[64],
                                            const unsigned long long (*Rs)[64],
                                            unsigned long long (*a1)[4],
                                            unsigned long long (*a2)[4],
                                            int r0, int c0) {
#pragma unroll 4
    for (int kk = 0; kk < 64; kk++) {
        unsigned long long axx[4], ayy[4];
#pragma unroll
        for (int d = 0; d < 4; d++) {
            float2 a = Ls[r0 + d][kk];
            axx[d] = pack2(a.x, a.x);
            ayy[d] = pack2(a.y, a.y);
        }
        ulonglong2 b01 = *(const ulonglong2*)&Rs[kk][c0];
        ulonglong2 b23 = *(const ulonglong2*)&Rs[kk][c0 + 2];
        unsigned long long b0 = b01.x, b1 = b01.y, b2 = b23.x, b3 = b23.y;
#pragma unroll
        for (int d = 0; d < 4; d++) {
            ffma2(a1[d][0], axx[d], b0); ffma2(a2[d][0], ayy[d], b0);
            ffma2(a1[d][1], axx[d], b1); ffma2(a2[d][1], ayy[d], b1);
            ffma2(a1[d][2], axx[d], b2); ffma2(a2[d][2], ayy[d], b2);
            ffma2(a1[d][3], axx[d], b3); ffma2(a2[d][3], ayy[d], b3);
        }
    }
}

__device__ __forceinline__ void cgemm2_store(unsigned long long (*a1)[4],
                                             unsigned long long (*a2)[4],
                                             float2* rowbase0, int rowstride_f2,
                                             int c0) {
#pragma unroll
    for (int d = 0; d < 4; d++) {
        float x0, y0, x1, y1, x2, y2, x3, y3;
        float p0, q0, p1, q1, p2, q2, p3, q3;
        unpack2(a1[d][0], x0, y0); unpack2(a2[d][0], p0, q0);
        unpack2(a1[d][1], x1, y1); unpack2(a2[d][1], p1, q1);
        unpack2(a1[d][2], x2, y2); unpack2(a2[d][2], p2, q2);
        unpack2(a1[d][3], x3, y3); unpack2(a2[d][3], p3, q3);
        float2* row = rowbase0 + (size_t)d * rowstride_f2 + c0;
        *(float4*)&row[0] = make_float4(x0 - q0, y0 + p0, x1 - q1, y1 + p1);
        *(float4*)&row[2] = make_float4(x2 - q2, y2 + p2, x3 - q3, y3 + p3);
    }
}

// ---------------- mma.sync / ldmatrix helpers (non-'a' PTX, legal on sm_103) ----------------
__device__ __forceinline__ unsigned smem_u32(const void* p) {
    unsigned a;
    asm("{ .reg .u64 t; cvta.to.shared.u64 t, %1; cvt.u32.u64 %0, t; }" : "=r"(a) : "l"(p));
    return a;
}
__device__ __forceinline__ void ldsm4(unsigned* r, unsigned addr) {
    asm volatile("ldmatrix.sync.aligned.m8n8.x4.shared.b16 {%0,%1,%2,%3}, [%4];"
        : "=r"(r[0]), "=r"(r[1]), "=r"(r[2]), "=r"(r[3]) : "r"(addr));
}
__device__ __forceinline__ void mma16816(float* c, const unsigned* a, const unsigned* b) {
    asm volatile("mma.sync.aligned.m16n8k16.row.col.f32.bf16.bf16.f32 "
        "{%0,%1,%2,%3}, {%4,%5,%6,%7}, {%8,%9}, {%0,%1,%2,%3};"
        : "+f"(c[0]), "+f"(c[1]), "+f"(c[2]), "+f"(c[3])
        : "r"(a[0]), "r"(a[1]), "r"(a[2]), "r"(a[3]), "r"(b[0]), "r"(b[1]));
}

// 3-way bf16 split
__device__ __forceinline__ void bsplit(float x, unsigned short& h,
                                       unsigned short& m, unsigned short& l) {
    __nv_bfloat16 bh = __float2bfloat16(x);
    float r1 = x - __bfloat162float(bh);
    __nv_bfloat16 bm = __float2bfloat16(r1);
    float r2 = r1 - __bfloat162float(bm);
    __nv_bfloat16 bl = __float2bfloat16(r2);
    h = __bfloat16_as_ushort(bh); m = __bfloat16_as_ushort(bm); l = __bfloat16_as_ushort(bl);
}
__device__ __forceinline__ unsigned pkw(unsigned short a, unsigned short b) {
    return (unsigned)a | ((unsigned)b << 16);
}

// ---------------- small/fused kernels (unchanged, proven) ----------------

__global__ void k_cell(const float* __restrict__ gene) {
    __shared__ float part[256];
    int b = blockIdx.x, t = threadIdx.x;
    int h = t & 63, chunk = t >> 6;
    const float* base = gene + ((size_t)b*Nn + chunk*256)*Hh + h;
    float s = 0.f;
    for (int n = 0; n < 256; n++) s += base[(size_t)n*Hh];
    part[t] = s;
    __syncthreads();
    if (t < 64)
        g_cell[b][t] = (part[t] + part[t+64] + part[t+128] + part[t+192]) * (1.0f/1024.0f);
}

__global__ __launch_bounds__(256) void k_mlp(
    const float* __restrict__ gene, const float* __restrict__ coh,
    const float* __restrict__ gb,
    const float* __restrict__ ew1, const float* __restrict__ eb1,
    const float* __restrict__ ew2, const float* __restrict__ eb2,
    const float* __restrict__ ow1, const float* __restrict__ ob1,
    const float* __restrict__ ow2, const float* __restrict__ ob2,
    float* __restrict__ out)
{
    __shared__ float swe[64][32], swo[64][32];
    __shared__ float sg[8][64];
    __shared__ float sw2e[32], sw2o[32];
    int t = threadIdx.x;
#pragma unroll
    for (int s = 0; s < 8; s++) {
        int e = t + 256*s;
        swe[e>>5][e&31] = ew1[e];
        swo[e>>5][e&31] = ow1[e];
    }
    if (t < 32) { sw2e[t] = ew2[t]; sw2o[t] = ow2[t]; }
    __syncthreads();

    int w = t >> 5, lane = t & 31;
    int row = blockIdx.x * 8 + w;
    int b = row >> 10, n = row & (Nn-1);

    const float* grow = gene + (size_t)row*Hh;
    sg[w][lane]    = grow[lane];
    sg[w][lane+32] = grow[lane+32];
    __syncwarp();

    float ae = eb1[lane], ao = ob1[lane];
#pragma unroll
    for (int h = 0; h < 64; h++) {
        float g = sg[w][h];
        ae = fmaf(g, swe[h][lane], ae);
        ao = fmaf(g, swo[h][lane], ao);
    }
    float h1 = ae / (1.0f + expf(-ae));
    float o1 = ao / (1.0f + expf(-ao));
    float ve = h1 * sw2e[lane];
    float vo = o1 * sw2o[lane];
    float cs = sg[w][lane] + sg[w][lane+32];
#pragma unroll
    for (int off = 16; off; off >>= 1) {
        ve += __shfl_xor_sync(0xffffffffu, ve, off);
        vo += __shfl_xor_sync(0xffffffffu, vo, off);
        cs += __shfl_xor_sync(0xffffffffu, cs, off);
    }
    float env   = 1.0f / (1.0f + expf(-(ve + eb2[0])));
    float omega = vo + ob2[0];
    float gamma = (1.0f / (1.0f + expf(-gb[n]))) * (1.0f + env);
    float classical = cs * (1.0f/64.0f);

    if (lane == 0) {
        out[GAMMA_OFF + row] = gamma;
        g_omega[b][n] = omega;
    }
    float om1 = 1.0f - gamma;
    const float* crow = coh + (size_t)row*Hh;
    float* drow = out + DEC_OFF + (size_t)row*Hh;
    drow[lane]    = om1*crow[lane]    + gamma*classical;
    drow[lane+32] = om1*crow[lane+32] + gamma*classical;
}

__global__ void k_omred() {
    __shared__ float s[256];
    int b = blockIdx.x, t = threadIdx.x;
    s[t] = g_omega[b][t] + g_omega[b][t+256] + g_omega[b][t+512] + g_omega[b][t+768];
    __syncthreads();
    for (int off = 128; off; off >>= 1) { if (t < off) s[t] += s[t+off]; __syncthreads(); }
    if (t == 0) g_wre[b] = s[0] * (1.0f/1024.0f);
}

__global__ void k_probs(const float* __restrict__ emb, float* __restrict__ out) {
    int t = threadIdx.x;
    if (t >= 16) return;
    float nc = 0.f, d0 = 0.f, d1 = 0.f, n0 = 0.f, n1 = 0.f;
    for (int d = 0; d < 64; d++) {
        float c = g_cell[t][d];
        float e0 = emb[d], e1 = emb[64 + d];
        nc = fmaf(c, c, nc); d0 = fmaf(c, e0, d0); d1 = fmaf(c, e1, d1);
        n0 = fmaf(e0, e0, n0); n1 = fmaf(e1, e1, n1);
    }
    float ic = 1.0f / fmaxf(sqrtf(nc), 1e-12f);
    float l0 = d0 * ic / fmaxf(sqrtf(n0), 1e-12f) * 10.0f;
    float l1 = d1 * ic / fmaxf(sqrtf(n1), 1e-12f) * 10.0f;
    float m = fmaxf(l0, l1);
    float p0 = expf(l0 - m), p1 = expf(l1 - m);
    float is = 1.0f / (p0 + p1);
    out[SP_OFF + t*2 + 0] = p0 * is;
    out[SP_OFF + t*2 + 1] = p1 * is;
}

__global__ void k_sym(const float* __restrict__ Hm) {
    __shared__ float tile[32][33];
    int bx = blockIdx.x, by = blockIdx.y;
    int tx = threadIdx.x, ty = threadIdx.y;
#pragma unroll
    for (int s = 0; s < 32; s += 8)
        tile[ty+s][tx] = Hm[(size_t)(bx*32 + ty + s)*Nn + by*32 + tx];
    __syncthreads();
#pragma unroll
    for (int s = 0; s < 32; s += 8) {
        int i = by*32 + ty + s, j = bx*32 + tx;
        g_Hs[i][j] = 0.5f * (Hm[(size_t)i*Nn + j] + tile[tx][ty+s]);
    }
}

__global__ void k_build() {
    int i = blockIdx.x, b = blockIdx.y, t = threadIdx.x;
    float wre = g_wre[b];
#pragma unroll
    for (int s = 0; s < 4; s++) {
        int j = t + 256*s;
        float re = ((i == j) ? wre : 0.0f) - g_Hs[i][j];
        g_A[b][i][j] = make_float2(re, (i == j) ? ETA_ : 0.0f);
    }
}

// ---------------- blocked Gauss-Jordan ----------------

__global__ __launch_bounds__(256) void k_diag(int kb) {
    __shared__ float2 M[64][64];
    int b = blockIdx.x, t = threadIdx.x;
    int kbase = kb * NB;
#pragma unroll
    for (int s = 0; s < 16; s++) {
        int e = t + 256*s; int r = e >> 6, c = e & 63;
        M[r][c] = g_A[b][kbase + r][kbase + c];
    }
    __syncthreads();
    int jj = t & 63, i0 = t >> 6;
    for (int k = 0; k < 64; k++) {
        float2 p = M[k][k];
        float id = 1.0f / (p.x*p.x + p.y*p.y);
        float2 pinv = make_float2(p.x*id, -p.y*id);
        float2 rk = M[k][jj];
        float2 f[16];
#pragma unroll
        for (int m = 0; m < 16; m++) f[m] = M[i0 + 4*m][k];
        __syncthreads();
        float2 nrk;
        if (jj == k) nrk = pinv;
        else nrk = make_float2(rk.x*pinv.x - rk.y*pinv.y, rk.x*pinv.y + rk.y*pinv.x);
#pragma unroll
        for (int m = 0; m < 16; m++) {
            int i = i0 + 4*m;
            if (i == k) {
                M[k][jj] = nrk;
            } else if (jj == k) {
                M[i][k] = make_float2(-(f[m].x*pinv.x - f[m].y*pinv.y),
                                      -(f[m].x*pinv.y + f[m].y*pinv.x));
            } else {
                float2 v = M[i][jj];
                v.x -= f[m].x*nrk.x - f[m].y*nrk.y;
                v.y -= f[m].x*nrk.y + f[m].y*nrk.x;
                M[i][jj] = v;
            }
        }
        __syncthreads();
    }
#pragma unroll
    for (int s = 0; s < 16; s++) {
        int e = t + 256*s; int r = e >> 6, c = e & 63;
        g_A[b][kbase + r][kbase + c] = M[r][c];
    }
}

// row-block scale: A[k, jt] <- P @ A[k, jt]  (jt != kb), FFMA2 path (proven)
__global__ __launch_bounds__(256, 2) void k_rowscale(int kb) {
    int jt = blockIdx.x, b = blockIdx.y;
    if (jt == kb) return;
    __shared__ __align__(16) float2 Ls[64][64];
    __shared__ __align__(16) unsigned long long Rs[64][64];
    int t = threadIdx.x;
    int kbase = kb * NB, jbase = jt * NB;
#pragma unroll
    for (int s = 0; s < 16; s++) {
        int e = t + 256*s; int r = e >> 6, c = e & 63;
        Ls[r][c] = g_A[b][kbase + r][kbase + c];
        Rs[r][c] = *(const unsigned long long*)&g_A[b][kbase + r][jbase + c];
    }
    __syncthreads();
    int tx = t & 15, ty = t >> 4, r0 = ty*4, c0 = tx*4;
    unsigned long long a1[4][4], a2[4][4];
#pragma unroll
    for (int d = 0; d < 4; d++)
#pragma unroll
        for (int c = 0; c < 4; c++) { a1[d][c] = 0ULL; a2[d][c] = 0ULL; }
    cgemm2_body(Ls, Rs, a1, a2, r0, c0);
    cgemm2_store(a1, a2, &g_A[b][kbase + r0][jbase], Nn, c0);
}

// F snapshot + split: column kb of A (kb rows zeroed) -> 6 swizzled bf16 tiles per (b, mt)
__global__ void k_fsplit(int kb) {
    int mt = blockIdx.x, b = blockIdx.y, t = threadIdx.x;
    char* tb = (char*)&g_FS[b][mt][0][0][0];
#pragma unroll
    for (int i = 0; i < 16; i++) {
        int e = t + 256*i;             // 0..4095
        int r = e >> 5, kp = e & 31;   // row 0..127, k-pair 0..31
        int grow = mt*128 + r;
        float4 v = *(const float4*)&g_A[b][grow][kb*NB + 2*kp];
        if ((grow >> 6) == kb) v = make_float4(0.f, 0.f, 0.f, 0.f);
        unsigned short h0,m0,l0,h1,m1,l1,hi0,mi0,li0,hi1,mi1,li1;
        bsplit(v.x, h0, m0, l0);   bsplit(v.z, h1, m1, l1);
        bsplit(v.y, hi0, mi0, li0); bsplit(v.w, hi1, mi1, li1);
        unsigned off = (unsigned)(r*128 + (((kp>>2) ^ (r & 7)) << 4) + ((kp & 3) << 2));
        *(unsigned*)(tb + 0*16384 + off) = pkw(h0,  h1);
        *(unsigned*)(tb + 1*16384 + off) = pkw(m0,  m1);
        *(unsigned*)(tb + 2*16384 + off) = pkw(l0,  l1);
        *(unsigned*)(tb + 3*16384 + off) = pkw(hi0, hi1);
        *(unsigned*)(tb + 4*16384 + off) = pkw(mi0, mi1);
        *(unsigned*)(tb + 5*16384 + off) = pkw(li0, li1);
    }
}

// Rk split: post-rowscale rows kb (incl col kb = P) -> 9 swizzled bf16 [n][k] tiles per (b, jt)
__global__ void k_bsplit(int kb) {
    int jt = blockIdx.x, b = blockIdx.y, t = threadIdx.x;
    char* tb = (char*)&g_BS[b][jt][0][0][0];
#pragma unroll
    for (int i = 0; i < 8; i++) {
        int e = t + 256*i;             // 0..2047
        int n = e >> 5, kp = e & 31;   // n 0..63, k-pair 0..31
        float2 v0 = g_A[b][kb*NB + 2*kp    ][jt*NB + n];
        float2 v1 = g_A[b][kb*NB + 2*kp + 1][jt*NB + n];
        unsigned short h0,m0,l0,h1,m1,l1,hi0,mi0,li0,hi1,mi1,li1;
        bsplit(v0.x, h0, m0, l0);   bsplit(v1.x, h1, m1, l1);
        bsplit(v0.y, hi0, mi0, li0); bsplit(v1.y, hi1, mi1, li1);
        unsigned off = (unsigned)(n*128 + (((kp>>2) ^ (n & 7)) << 4) + ((kp & 3) << 2));
        unsigned rh = pkw(h0,  h1), rm = pkw(m0,  m1), rl = pkw(l0,  l1);
        unsigned ih = pkw(hi0, hi1), im_ = pkw(mi0, mi1), il = pkw(li0, li1);
        *(unsigned*)(tb + 0*8192 + off) = rh;
        *(unsigned*)(tb + 1*8192 + off) = rm;
        *(unsigned*)(tb + 2*8192 + off) = rl;
        *(unsigned*)(tb + 3*8192 + off) = ih;
        *(unsigned*)(tb + 4*8192 + off) = im_;
        *(unsigned*)(tb + 5*8192 + off) = il;
        *(unsigned*)(tb + 6*8192 + off) = ih  ^ 0x80008000u;   // -Ri
        *(unsigned*)(tb + 7*8192 + off) = im_ ^ 0x80008000u;
        *(unsigned*)(tb + 8*8192 + off) = il  ^ 0x80008000u;
    }
}

// ---------------- HMMA trailing update ----------------
#define SMB_OFF 98304u     // B tiles after 6*16384 of A tiles
#define SMEM_UPD (98304 + 9*8192)   // 172032

#define GEMM_BODY(ACC)                                                            \
    _Pragma("unroll")                                                             \
    for (int ks = 0; ks < 4; ks++) {                                              \
        unsigned af[2][4], bf[2][4];                                              \
        _Pragma("unroll")                                                         \
        for (int mf = 0; mf < 2; mf++) {                                          \
            int row = m0 + mf*16 + aRow;                                          \
            unsigned ad = abase + row*128 + (((ks*2 + aKc) ^ (row & 7)) << 4);    \
            ldsm4(af[mf], ad);                                                    \
        }                                                                         \
        _Pragma("unroll")                                                         \
        for (int nf = 0; nf < 2; nf++) {                                          \
            int nr = n0 + nf*16 + bRow;                                           \
            unsigned bd = bbase + nr*128 + (((ks*2 + bKc) ^ (nr & 7)) << 4);      \
            ldsm4(bf[nf], bd);                                                    \
        }                                                                         \
        _Pragma("unroll")                                                         \
        for (int mf = 0; mf < 2; mf++)                                            \
            _Pragma("unroll")                                                     \
            for (int nb = 0; nb < 4; nb++)                                        \
                mma16816(&ACC[(mf*4 + nb)*4], af[mf], &bf[nb>>1][(nb&1)*2]);      \
    }

__global__ __launch_bounds__(256, 1) void k_update_mma(int kb) {
    extern __shared__ char smem[];
    int t = threadIdx.x;
    int jt = blockIdx.x, mt = blockIdx.y, b = blockIdx.z;

    // bulk copy of preswizzled split tiles: A 96KB + B 72KB
    {
        const uint4* sA = (const uint4*)&g_FS[b][mt][0][0][0];
        uint4* dA = (uint4*)smem;
#pragma unroll 4
        for (int i = t; i < 6144; i += 256) dA[i] = sA[i];
        const uint4* sB = (const uint4*)&g_BS[b][jt][0][0][0];
        uint4* dB = (uint4*)(smem + SMB_OFF);
#pragma unroll 4
        for (int i = t; i < 4608; i += 256) dB[i] = sB[i];
    }
    __syncthreads();

    int w = t >> 5, lane = t & 31;
    int m0 = (w >> 1) * 32, n0 = (w & 1) * 32;

    // lane-constant ldmatrix address pieces
    int mi = lane >> 3, ri = lane & 7;
    int aRow = ri + ((mi & 1) << 3);
    int aKc  = mi >> 1;
    int bRow = ri + ((mi >> 1) << 3);
    int bKc  = mi & 1;

    unsigned smA = smem_u32(smem);
    unsigned smB = smA + SMB_OFF;

    float accR[32], accI[32];
#pragma unroll
    for (int i = 0; i < 32; i++) { accR[i] = 0.f; accI[i] = 0.f; }

    for (int p = 0; p < 24; p++) {
        unsigned abase = smA + (unsigned)c_sa[p] * 16384u;
        unsigned bbase = smB + (unsigned)c_sb[p] * 8192u;
        if (c_ac[p]) { GEMM_BODY(accI) } else { GEMM_BODY(accR) }
    }

    // epilogue: C_new = old - D  (jt==kb column: C_new = -D); kb block-rows untouched
    bool diagcol = (jt == kb);
    int jb = jt * NB;
    int grb = mt*128 + m0;
#pragma unroll
    for (int mf = 0; mf < 2; mf++) {
        int r0 = grb + mf*16 + (lane >> 2);
        if ((r0 >> 6) == kb) continue;
#pragma unroll
        for (int nb = 0; nb < 4; nb++) {
            int col = n0 + nb*8 + 2*(lane & 3);
            int i0 = (mf*4 + nb)*4;
#pragma unroll
            for (int hr = 0; hr < 2; hr++) {
                int gr = r0 + hr*8;
                int iq = i0 + hr*2;
                float4* p4 = (float4*)&g_A[b][gr][jb + col];
                float4 nv;
                if (diagcol) {
                    nv = make_float4(-accR[iq], -accI[iq], -accR[iq+1], -accI[iq+1]);
                } else {
                    float4 o = *p4;
                    nv = make_float4(o.x - accR[iq], o.y - accI[iq],
                                     o.z - accR[iq+1], o.w - accI[iq+1]);
                }
                *p4 = nv;
            }
        }
    }
}

// propagator = |A^{-1}| elementwise
__global__ void k_abs(float* __restrict__ out) {
    int idx = blockIdx.x * 256 + threadIdx.x;
    const float4* A4 = (const float4*)g_A;
    float4 u0 = A4[idx*2], u1 = A4[idx*2 + 1];
    float4 o;
    float s0 = u0.x*u0.x + u0.y*u0.y; o.x = s0 > 0.f ? s0 * rsqrtf(s0) : 0.f;
    float s1 = u0.z*u0.z + u0.w*u0.w; o.y = s1 > 0.f ? s1 * rsqrtf(s1) : 0.f;
    float s2 = u1.x*u1.x + u1.y*u1.y; o.z = s2 > 0.f ? s2 * rsqrtf(s2) : 0.f;
    float s3 = u1.z*u1.z + u1.w*u1.w; o.w = s3 > 0.f ? s3 * rsqrtf(s3) : 0.f;
    ((float4*)(out + PROP_OFF))[idx] = o;
}

// ---------------- launch ----------------
extern "C" void kernel_launch(void* const* d_in, const int* in_sizes, int n_in,
                              void* d_out, int out_size) {
    const float* gene = (const float*)d_in[0];
    const float* coh  = (const float*)d_in[1];
    const float* emb  = (const float*)d_in[2];
    const float* gb   = (const float*)d_in[3];
    const float* ew1  = (const float*)d_in[4];
    const float* eb1  = (const float*)d_in[5];
    const float* ew2  = (const float*)d_in[6];
    const float* eb2  = (const float*)d_in[7];
    const float* ow1  = (const float*)d_in[8];
    const float* ob1  = (const float*)d_in[9];
    const float* ow2  = (const float*)d_in[10];
    const float* ob2  = (const float*)d_in[11];
    const float* Hm   = (const float*)d_in[12];
    float* out = (float*)d_out;

    static int smem_set = 0;
    if (!smem_set) {
        cudaFuncSetAttribute(k_update_mma, cudaFuncAttributeMaxDynamicSharedMemorySize, SMEM_UPD);
        smem_set = 1;
    }

    k_cell<<<Bz, 256>>>(gene);
    k_mlp<<<(Bz*Nn)/8, 256>>>(gene, coh, gb, ew1, eb1, ew2, eb2, ow1, ob1, ow2, ob2, out);
    k_probs<<<1, 32>>>(emb, out);
    k_omred<<<Bz, 256>>>();
    k_sym<<<dim3(32, 32), dim3(32, 8)>>>(Hm);
    k_build<<<dim3(Nn, Bz), 256>>>();

    for (int kb = 0; kb < NT; kb++) {
        k_diag<<<Bz, 256>>>(kb);
        k_fsplit<<<dim3(8, Bz), 256>>>(kb);
        k_rowscale<<<dim3(NT, Bz), 256>>>(kb);
        k_bsplit<<<dim3(NT, Bz), 256>>>(kb);
        k_update_mma<<<dim3(NT, 8, Bz), 256, SMEM_UPD>>>(kb);
    }
    k_abs<<<(Bz*Nn*Nn)/(256*4), 256>>>(out);
}